// round 1
// baseline (speedup 1.0000x reference)
#include <cuda_runtime.h>
#include <math.h>
#include <stdint.h>

#define BN   256      // batch
#define PN   32768    // proxies
#define DN   256      // feature dim
#define CN   8        // cameras
#define KSCALE 20.0f  // 1/TEMP
#define BGK  50
#define PKK  3
#define BALW 0.15f

#define NEG_INF (__int_as_float(0xff800000))

// ---------------- scratch (static device memory: allowed) ----------------
__device__ float g_A[2 * BN * DN];             // rows 0..255 = features, 256..511 = mem[prx[b]]
__device__ int   g_prx[BN];
__device__ int   g_pseudo[BN];
__device__ float g_inputs[(size_t)BN * PN];    // 32 MB: score / TEMP
__device__ float g_sims[(size_t)BN * PN];      // 32 MB: 0.15*score + 0.85*mem[prx]@mem^T
__device__ float g_loss[3 * BN];               // intra / cross / online per sample

// monotonic float->uint key (order-preserving)
__device__ __forceinline__ unsigned fkey(float v) {
    unsigned u = __float_as_uint(v);
    return (u & 0x80000000u) ? ~u : (u | 0x80000000u);
}

// ---------------- K1: gather prx rows, build A ----------------
__global__ void k_prep(const float* __restrict__ features,
                       const int* __restrict__ targets,
                       const int* __restrict__ all_proxy_label,
                       const float* __restrict__ mem) {
    int b = blockIdx.x;
    int t = threadIdx.x;
    int tgt = targets[b];
    int prx = all_proxy_label[tgt];
    if (t == 0) { g_prx[b] = prx; g_pseudo[b] = prx / CN; }
    g_A[b * DN + t]        = features[b * DN + t];
    g_A[(BN + b) * DN + t] = mem[(size_t)prx * DN + t];
}

// ---------------- K2: fused dual GEMM ----------------
// CTA: 64 batch rows x 128 proxies, both halves (score & prxsim), K=256.
__global__ __launch_bounds__(256, 2) void k_gemm(const float* __restrict__ mem) {
    __shared__ float sAf[16][65];
    __shared__ float sAp[16][65];
    __shared__ float sB[16][132];

    const int t  = threadIdx.x;
    const int tx = t & 15;
    const int ty = t >> 4;
    const int p0 = blockIdx.x * 128;
    const int b0 = blockIdx.y * 64;

    float accF[4][8];
    float accP[4][8];
#pragma unroll
    for (int i = 0; i < 4; i++)
#pragma unroll
        for (int j = 0; j < 8; j++) { accF[i][j] = 0.f; accP[i][j] = 0.f; }

    const int ar  = t >> 2;          // 0..63
    const int akc = (t & 3) << 2;    // 0,4,8,12
    const float* gAf = g_A + (size_t)(b0 + ar) * DN + akc;
    const float* gAp = g_A + (size_t)(BN + b0 + ar) * DN + akc;

    for (int k0 = 0; k0 < DN; k0 += 16) {
        float4 va = *(const float4*)(gAf + k0);
        float4 vp = *(const float4*)(gAp + k0);
        sAf[akc + 0][ar] = va.x; sAf[akc + 1][ar] = va.y;
        sAf[akc + 2][ar] = va.z; sAf[akc + 3][ar] = va.w;
        sAp[akc + 0][ar] = vp.x; sAp[akc + 1][ar] = vp.y;
        sAp[akc + 2][ar] = vp.z; sAp[akc + 3][ar] = vp.w;
#pragma unroll
        for (int s = 0; s < 2; s++) {
            int idx = t + 256 * s;
            int r   = idx >> 2;
            int kc  = (idx & 3) << 2;
            float4 vb = *(const float4*)(mem + (size_t)(p0 + r) * DN + k0 + kc);
            sB[kc + 0][r] = vb.x; sB[kc + 1][r] = vb.y;
            sB[kc + 2][r] = vb.z; sB[kc + 3][r] = vb.w;
        }
        __syncthreads();
#pragma unroll
        for (int kk = 0; kk < 16; kk++) {
            float af[4], ap[4], bb[8];
#pragma unroll
            for (int i = 0; i < 4; i++) {
                af[i] = sAf[kk][ty * 4 + i];
                ap[i] = sAp[kk][ty * 4 + i];
            }
            float4 b0v = *(const float4*)&sB[kk][tx * 4];
            float4 b1v = *(const float4*)&sB[kk][64 + tx * 4];
            bb[0] = b0v.x; bb[1] = b0v.y; bb[2] = b0v.z; bb[3] = b0v.w;
            bb[4] = b1v.x; bb[5] = b1v.y; bb[6] = b1v.z; bb[7] = b1v.w;
#pragma unroll
            for (int i = 0; i < 4; i++)
#pragma unroll
                for (int j = 0; j < 8; j++) {
                    accF[i][j] = fmaf(af[i], bb[j], accF[i][j]);
                    accP[i][j] = fmaf(ap[i], bb[j], accP[i][j]);
                }
        }
        __syncthreads();
    }

#pragma unroll
    for (int i = 0; i < 4; i++) {
        int b = b0 + ty * 4 + i;
        float* rin = g_inputs + (size_t)b * PN + p0;
        float* rsm = g_sims   + (size_t)b * PN + p0;
        float4 o;
        o.x = KSCALE * accF[i][0]; o.y = KSCALE * accF[i][1];
        o.z = KSCALE * accF[i][2]; o.w = KSCALE * accF[i][3];
        *(float4*)(rin + tx * 4) = o;
        o.x = KSCALE * accF[i][4]; o.y = KSCALE * accF[i][5];
        o.z = KSCALE * accF[i][6]; o.w = KSCALE * accF[i][7];
        *(float4*)(rin + 64 + tx * 4) = o;
        o.x = BALW * accF[i][0] + (1.0f - BALW) * accP[i][0];
        o.y = BALW * accF[i][1] + (1.0f - BALW) * accP[i][1];
        o.z = BALW * accF[i][2] + (1.0f - BALW) * accP[i][2];
        o.w = BALW * accF[i][3] + (1.0f - BALW) * accP[i][3];
        *(float4*)(rsm + tx * 4) = o;
        o.x = BALW * accF[i][4] + (1.0f - BALW) * accP[i][4];
        o.y = BALW * accF[i][5] + (1.0f - BALW) * accP[i][5];
        o.z = BALW * accF[i][6] + (1.0f - BALW) * accP[i][6];
        o.w = BALW * accF[i][7] + (1.0f - BALW) * accP[i][7];
        *(float4*)(rsm + 64 + tx * 4) = o;
    }
}

// ---------------- K3: intra loss ----------------
// intra_b = lse(inputs[b, p : p % 8 == cams[b]]) - inputs[b, prx[b]]
__global__ __launch_bounds__(256) void k_intra(const int* __restrict__ cams) {
    __shared__ float red[256];
    int b = blockIdx.x, t = threadIdx.x;
    const float* row = g_inputs + (size_t)b * PN;
    int cam = cams[b];
    float v[16];
#pragma unroll
    for (int i = 0; i < 16; i++) v[i] = row[cam + 8 * (t + 256 * i)];
    float m = NEG_INF;
#pragma unroll
    for (int i = 0; i < 16; i++) m = fmaxf(m, v[i]);
    red[t] = m; __syncthreads();
    for (int off = 128; off > 0; off >>= 1) {
        if (t < off) red[t] = fmaxf(red[t], red[t + off]);
        __syncthreads();
    }
    m = red[0]; __syncthreads();
    float s = 0.f;
#pragma unroll
    for (int i = 0; i < 16; i++) s += expf(v[i] - m);
    red[t] = s; __syncthreads();
    for (int off = 128; off > 0; off >>= 1) {
        if (t < off) red[t] += red[t + off];
        __syncthreads();
    }
    if (t == 0) g_loss[b] = m + logf(red[0]) - row[g_prx[b]];
}

// ---------------- K4: cross loss ----------------
// top-50 of inputs excluding 8 pos indices; lse over 50+8; minus mean(pos)
__global__ __launch_bounds__(256) void k_cross() {
    __shared__ unsigned hist[2048];
    __shared__ float    cand[2048];
    __shared__ unsigned sa[256], sb2[256];
    __shared__ float    red[256];
    __shared__ float    sposv[8];
    __shared__ float    sM;
    __shared__ int      sh_bstar, sh_cntgt;
    __shared__ unsigned sh_ncand;

    int b = blockIdx.x, t = threadIdx.x;
    const float* row = g_inputs + (size_t)b * PN;
    int pseudo = g_pseudo[b];

    for (int i = t; i < 2048; i += 256) hist[i] = 0;
    if (t == 0) sh_ncand = 0;
    if (t < 8) sposv[t] = row[pseudo * 8 + t];
    __syncthreads();

    float m = NEG_INF;
    for (int p = t; p < PN; p += 256) {
        if ((p >> 3) == pseudo) continue;
        float v = row[p];
        m = fmaxf(m, v);
        atomicAdd(&hist[fkey(v) >> 21], 1u);
    }
    red[t] = m; __syncthreads();
    for (int off = 128; off > 0; off >>= 1) {
        if (t < off) red[t] = fmaxf(red[t], red[t + off]);
        __syncthreads();
    }
    if (t == 0) {
        float mm = red[0];
        for (int k = 0; k < 8; k++) mm = fmaxf(mm, sposv[k]);
        sM = mm;
    }
    __syncthreads();
    float M = sM;

    // boundary bin for top-BGK
    unsigned cs = 0;
    for (int g = 0; g < 8; g++) cs += hist[t * 8 + g];
    sa[t] = cs; __syncthreads();
    unsigned* src = sa; unsigned* dst = sb2;
    for (int off = 1; off < 256; off <<= 1) {
        unsigned x = src[t] + ((t + off < 256) ? src[t + off] : 0u);
        __syncthreads();
        dst[t] = x; __syncthreads();
        unsigned* tmp = src; src = dst; dst = tmp;
    }
    unsigned running = (t < 255) ? src[t + 1] : 0u;
    for (int g = 7; g >= 0; g--) {
        int bin = t * 8 + g;
        unsigned h = hist[bin];
        if (running < (unsigned)BGK && running + h >= (unsigned)BGK) {
            sh_bstar = bin; sh_cntgt = (int)running;
        }
        running += h;
    }
    __syncthreads();
    int bstar = sh_bstar, needc = BGK - sh_cntgt;

    float sloc = 0.f;
    for (int p = t; p < PN; p += 256) {
        if ((p >> 3) == pseudo) continue;
        float v = row[p];
        int bin = (int)(fkey(v) >> 21);
        if (bin > bstar) sloc += expf(v - M);
        else if (bin == bstar) {
            unsigned i = atomicAdd(&sh_ncand, 1u);
            if (i < 2048u) cand[i] = v;
        }
    }
    __syncthreads();
    int nc = (int)min(sh_ncand, 2048u);
    for (int i = t; i < nc; i += 256) {
        float v = cand[i];
        int r = 0;
        for (int j = 0; j < nc; j++) {
            float w = cand[j];
            r += (w > v) || (w == v && j < i);
        }
        if (r < needc) sloc += expf(v - M);
    }
    if (t < 8) sloc += expf(sposv[t] - M);
    red[t] = sloc; __syncthreads();
    for (int off = 128; off > 0; off >>= 1) {
        if (t < off) red[t] += red[t + off];
        __syncthreads();
    }
    if (t == 0) {
        float psum = 0.f;
        for (int k = 0; k < 8; k++) psum += sposv[k];
        g_loss[BN + b] = M + logf(red[0]) - psum * 0.125f;
    }
}

// ---------------- K5: online loss ----------------
// per-camera argmax of sims -> top-3 cameras -> chosen proxies; top-50 of sims
// excluding chosen (indices!); gather INPUTS at the 53 indices; lse - mean(inputs[chosen]).
__global__ __launch_bounds__(256) void k_online() {
    __shared__ unsigned hist[2048];
    __shared__ float    scv[8 * 256];
    __shared__ int      sci[8 * 256];
    __shared__ float    candv[1024];
    __shared__ int      candi[1024];
    __shared__ int      above[64];
    __shared__ int      fin[64];
    __shared__ unsigned sa[256], sb2[256];
    __shared__ float    red[256];
    __shared__ float    cam_v[8];
    __shared__ int      cam_i[8];
    __shared__ int      chos[3];
    __shared__ float    chosv[3];
    __shared__ int      sh_bstar, sh_cntgt;
    __shared__ unsigned sh_nc, sh_na, sh_nf;

    int b = blockIdx.x, t = threadIdx.x;
    const float* rs = g_sims   + (size_t)b * PN;
    const float* ri = g_inputs + (size_t)b * PN;

    for (int i = t; i < 2048; i += 256) hist[i] = 0;
    if (t == 0) { sh_nc = 0; sh_na = 0; }
    float bv[8]; int bi[8];
#pragma unroll
    for (int c = 0; c < 8; c++) { bv[c] = NEG_INF; bi[c] = 0x7fffffff; }
    __syncthreads();

    for (int p = t; p < PN; p += 256) {
        float v = rs[p];
        int c = p & 7;
        if (v > bv[c]) { bv[c] = v; bi[c] = p; }  // ascending p: first max kept
        atomicAdd(&hist[fkey(v) >> 21], 1u);
    }
#pragma unroll
    for (int c = 0; c < 8; c++) { scv[c * 256 + t] = bv[c]; sci[c * 256 + t] = bi[c]; }
    __syncthreads();

    int w = t >> 5, l = t & 31;
    {
        float best = NEG_INF; int bidx = 0x7fffffff;
        for (int q = l; q < 256; q += 32) {
            float v = scv[w * 256 + q]; int i = sci[w * 256 + q];
            if (v > best || (v == best && i < bidx)) { best = v; bidx = i; }
        }
        for (int off = 16; off > 0; off >>= 1) {
            float ov = __shfl_down_sync(0xffffffffu, best, off);
            int   oi = __shfl_down_sync(0xffffffffu, bidx, off);
            if (ov > best || (ov == best && oi < bidx)) { best = ov; bidx = oi; }
        }
        if (l == 0) { cam_v[w] = best; cam_i[w] = bidx; }
    }
    __syncthreads();

    if (t == 0) {
        bool used[8] = {false,false,false,false,false,false,false,false};
        for (int k = 0; k < PKK; k++) {
            int bc = -1; float bvv = NEG_INF;
            for (int c = 0; c < 8; c++) {
                if (!used[c] && cam_v[c] > bvv) { bvv = cam_v[c]; bc = c; }
            }
            used[bc] = true;
            chos[k] = cam_i[bc]; chosv[k] = bvv;
        }
        for (int k = 0; k < PKK; k++) hist[fkey(chosv[k]) >> 21] -= 1;
    }
    __syncthreads();

    // boundary bin for top-BGK (chosen excluded via adjusted hist)
    unsigned cs = 0;
    for (int g = 0; g < 8; g++) cs += hist[t * 8 + g];
    sa[t] = cs; __syncthreads();
    unsigned* src = sa; unsigned* dst = sb2;
    for (int off = 1; off < 256; off <<= 1) {
        unsigned x = src[t] + ((t + off < 256) ? src[t + off] : 0u);
        __syncthreads();
        dst[t] = x; __syncthreads();
        unsigned* tmp = src; src = dst; dst = tmp;
    }
    unsigned running = (t < 255) ? src[t + 1] : 0u;
    for (int g = 7; g >= 0; g--) {
        int bin = t * 8 + g;
        unsigned h = hist[bin];
        if (running < (unsigned)BGK && running + h >= (unsigned)BGK) {
            sh_bstar = bin; sh_cntgt = (int)running;
        }
        running += h;
    }
    __syncthreads();
    int bstar = sh_bstar, needc = BGK - sh_cntgt;
    int c0 = chos[0], c1 = chos[1], c2 = chos[2];

    for (int p = t; p < PN; p += 256) {
        if (p == c0 || p == c1 || p == c2) continue;
        float v = rs[p];
        int bin = (int)(fkey(v) >> 21);
        if (bin > bstar) {
            unsigned i = atomicAdd(&sh_na, 1u);
            if (i < 64u) above[i] = p;
        } else if (bin == bstar) {
            unsigned i = atomicAdd(&sh_nc, 1u);
            if (i < 1024u) { candv[i] = v; candi[i] = p; }
        }
    }
    __syncthreads();
    int na = (int)min(sh_na, 64u);
    int nc = (int)min(sh_nc, 1024u);
    if (t == 0) { sh_nf = 3 + (unsigned)na; fin[0] = c0; fin[1] = c1; fin[2] = c2; }
    __syncthreads();
    for (int i = t; i < na; i += 256) fin[3 + i] = above[i];
    for (int i = t; i < nc; i += 256) {
        float v = candv[i]; int pi = candi[i];
        int r = 0;
        for (int j = 0; j < nc; j++) {
            float wv = candv[j];
            r += (wv > v) || (wv == v && candi[j] < pi);
        }
        if (r < needc) {
            unsigned k = atomicAdd(&sh_nf, 1u);
            if (k < 64u) fin[k] = pi;
        }
    }
    __syncthreads();
    int nf = (int)min(sh_nf, 64u);   // should be 53

    float val = (t < nf) ? ri[fin[t]] : NEG_INF;
    red[t] = val; __syncthreads();
    for (int off = 128; off > 0; off >>= 1) {
        if (t < off) red[t] = fmaxf(red[t], red[t + off]);
        __syncthreads();
    }
    float m = red[0]; __syncthreads();
    red[t] = (t < nf) ? expf(val - m) : 0.f;
    __syncthreads();
    for (int off = 128; off > 0; off >>= 1) {
        if (t < off) red[t] += red[t + off];
        __syncthreads();
    }
    if (t == 0) {
        float csum = ri[c0] + ri[c1] + ri[c2];
        g_loss[2 * BN + b] = m + logf(red[0]) - csum * (1.0f / 3.0f);
    }
}

// ---------------- K6: deterministic camera-mean reduction ----------------
__global__ void k_final(const int* __restrict__ cams, float* __restrict__ out) {
    __shared__ float s[8];
    int t = threadIdx.x;
    if (t < 8) {
        float acc = 0.f; int n = 0;
        for (int b = 0; b < BN; b++) {
            if (cams[b] == t) {
                acc += g_loss[b] + g_loss[BN + b] + g_loss[2 * BN + b];
                n++;
            }
        }
        s[t] = (n > 0) ? acc / (float)n : 0.f;
    }
    __syncthreads();
    if (t == 0) {
        float tot = 0.f;
        for (int c = 0; c < 8; c++) tot += s[c];
        out[0] = tot;
    }
}

// ---------------- launch ----------------
extern "C" void kernel_launch(void* const* d_in, const int* in_sizes, int n_in,
                              void* d_out, int out_size) {
    const float* features        = (const float*)d_in[0];
    const int*   targets         = (const int*)d_in[1];
    const int*   cams            = (const int*)d_in[2];
    // d_in[3] = epoch (unused)
    const float* global_memory   = (const float*)d_in[4];
    // d_in[5] = all_pseudo_label (derived from proxy label; unused)
    const int*   all_proxy_label = (const int*)d_in[6];
    // d_in[7] = cam_proxies  (structure: cam_proxies[c][j] = c + 8j — used implicitly)
    // d_in[8] = label_proxies (structure: label_proxies[l][k] = 8l + k — used implicitly)
    float* out = (float*)d_out;

    k_prep<<<BN, DN>>>(features, targets, all_proxy_label, global_memory);
    dim3 gg(PN / 128, BN / 64);
    k_gemm<<<gg, 256>>>(global_memory);
    k_intra<<<BN, 256>>>(cams);
    k_cross<<<BN, 256>>>();
    k_online<<<BN, 256>>>();
    k_final<<<1, 32>>>(cams, out);
}

// round 2
// speedup vs baseline: 1.0597x; 1.0597x over previous
#include <cuda_runtime.h>
#include <math.h>
#include <stdint.h>

#define BN   256      // batch
#define PN   32768    // proxies
#define DN   256      // feature dim
#define CN   8        // cameras
#define KSCALE 20.0f  // 1/TEMP
#define BGK  50
#define PKK  3
#define BALW 0.15f

#define NEG_INF (__int_as_float(0xff800000))

// ---------------- scratch ----------------
__device__ float g_A[2 * BN * DN];
__device__ int   g_pseudo[BN];
__device__ float g_inputs[(size_t)BN * PN];    // 32 MB
__device__ float g_sims[(size_t)BN * PN];      // 32 MB
__device__ float g_loss[3 * BN];

__device__ __forceinline__ unsigned fkey(float v) {
    unsigned u = __float_as_uint(v);
    return (u & 0x80000000u) ? ~u : (u | 0x80000000u);
}

// ---------------- K1: gather prx rows ----------------
__global__ void k_prep(const float* __restrict__ features,
                       const int* __restrict__ targets,
                       const int* __restrict__ all_proxy_label,
                       const float* __restrict__ mem) {
    int b = blockIdx.x;
    int t = threadIdx.x;
    int tgt = targets[b];
    int prx = all_proxy_label[tgt];
    if (t == 0) { g_pseudo[b] = prx / CN; }
    g_A[b * DN + t]        = features[b * DN + t];
    g_A[(BN + b) * DN + t] = mem[(size_t)prx * DN + t];
}

// ---------------- K2: fused dual GEMM (unchanged) ----------------
__global__ __launch_bounds__(256, 2) void k_gemm(const float* __restrict__ mem) {
    __shared__ float sAf[16][65];
    __shared__ float sAp[16][65];
    __shared__ float sB[16][132];

    const int t  = threadIdx.x;
    const int tx = t & 15;
    const int ty = t >> 4;
    const int p0 = blockIdx.x * 128;
    const int b0 = blockIdx.y * 64;

    float accF[4][8];
    float accP[4][8];
#pragma unroll
    for (int i = 0; i < 4; i++)
#pragma unroll
        for (int j = 0; j < 8; j++) { accF[i][j] = 0.f; accP[i][j] = 0.f; }

    const int ar  = t >> 2;
    const int akc = (t & 3) << 2;
    const float* gAf = g_A + (size_t)(b0 + ar) * DN + akc;
    const float* gAp = g_A + (size_t)(BN + b0 + ar) * DN + akc;

    for (int k0 = 0; k0 < DN; k0 += 16) {
        float4 va = *(const float4*)(gAf + k0);
        float4 vp = *(const float4*)(gAp + k0);
        sAf[akc + 0][ar] = va.x; sAf[akc + 1][ar] = va.y;
        sAf[akc + 2][ar] = va.z; sAf[akc + 3][ar] = va.w;
        sAp[akc + 0][ar] = vp.x; sAp[akc + 1][ar] = vp.y;
        sAp[akc + 2][ar] = vp.z; sAp[akc + 3][ar] = vp.w;
#pragma unroll
        for (int s = 0; s < 2; s++) {
            int idx = t + 256 * s;
            int r   = idx >> 2;
            int kc  = (idx & 3) << 2;
            float4 vb = *(const float4*)(mem + (size_t)(p0 + r) * DN + k0 + kc);
            sB[kc + 0][r] = vb.x; sB[kc + 1][r] = vb.y;
            sB[kc + 2][r] = vb.z; sB[kc + 3][r] = vb.w;
        }
        __syncthreads();
#pragma unroll
        for (int kk = 0; kk < 16; kk++) {
            float af[4], ap[4], bb[8];
#pragma unroll
            for (int i = 0; i < 4; i++) {
                af[i] = sAf[kk][ty * 4 + i];
                ap[i] = sAp[kk][ty * 4 + i];
            }
            float4 b0v = *(const float4*)&sB[kk][tx * 4];
            float4 b1v = *(const float4*)&sB[kk][64 + tx * 4];
            bb[0] = b0v.x; bb[1] = b0v.y; bb[2] = b0v.z; bb[3] = b0v.w;
            bb[4] = b1v.x; bb[5] = b1v.y; bb[6] = b1v.z; bb[7] = b1v.w;
#pragma unroll
            for (int i = 0; i < 4; i++)
#pragma unroll
                for (int j = 0; j < 8; j++) {
                    accF[i][j] = fmaf(af[i], bb[j], accF[i][j]);
                    accP[i][j] = fmaf(ap[i], bb[j], accP[i][j]);
                }
        }
        __syncthreads();
    }

#pragma unroll
    for (int i = 0; i < 4; i++) {
        int b = b0 + ty * 4 + i;
        float* rin = g_inputs + (size_t)b * PN + p0;
        float* rsm = g_sims   + (size_t)b * PN + p0;
        float4 o;
        o.x = KSCALE * accF[i][0]; o.y = KSCALE * accF[i][1];
        o.z = KSCALE * accF[i][2]; o.w = KSCALE * accF[i][3];
        *(float4*)(rin + tx * 4) = o;
        o.x = KSCALE * accF[i][4]; o.y = KSCALE * accF[i][5];
        o.z = KSCALE * accF[i][6]; o.w = KSCALE * accF[i][7];
        *(float4*)(rin + 64 + tx * 4) = o;
        o.x = BALW * accF[i][0] + (1.0f - BALW) * accP[i][0];
        o.y = BALW * accF[i][1] + (1.0f - BALW) * accP[i][1];
        o.z = BALW * accF[i][2] + (1.0f - BALW) * accP[i][2];
        o.w = BALW * accF[i][3] + (1.0f - BALW) * accP[i][3];
        *(float4*)(rsm + tx * 4) = o;
        o.x = BALW * accF[i][4] + (1.0f - BALW) * accP[i][4];
        o.y = BALW * accF[i][5] + (1.0f - BALW) * accP[i][5];
        o.z = BALW * accF[i][6] + (1.0f - BALW) * accP[i][6];
        o.w = BALW * accF[i][7] + (1.0f - BALW) * accP[i][7];
        *(float4*)(rsm + 64 + tx * 4) = o;
    }
}

// ---------------- fused loss kernel: 512 threads, float4, all 3 losses ----
__global__ __launch_bounds__(512) void k_loss(const int* __restrict__ cams) {
    __shared__ unsigned hist[2048];
    __shared__ float    candv[1024];
    __shared__ int      candi[1024];
    __shared__ float    red[512];
    __shared__ unsigned sa[512], sb2[512];
    __shared__ float    sposv[8];
    __shared__ float    s_cv[8][16];
    __shared__ int      s_ci[8][16];
    __shared__ int      above[64];
    __shared__ int      fin[64];
    __shared__ int      chos[3];
    __shared__ float    chosv[3];
    __shared__ int      sh_bstar, sh_cnt;
    __shared__ unsigned sh_nc, sh_na, sh_nf;

    const int b = blockIdx.x, t = threadIdx.x;
    const int lane = t & 31, wid = t >> 5;
    const float* ri = g_inputs + (size_t)b * PN;
    const float* rs = g_sims   + (size_t)b * PN;
    const int pseudo = g_pseudo[b];
    const int cam = cams[b];

    for (int i = t; i < 2048; i += 512) hist[i] = 0;
    if (t == 0) sh_nc = 0;
    if (t < 8) sposv[t] = ri[pseudo * 8 + t];
    __syncthreads();

    // ============ PHASE A: inputs row (intra + cross) ============
    // pass 1: row max, intra-cam max, histogram excluding pseudo group
    float m = NEG_INF, mi = NEG_INF;
#pragma unroll
    for (int i = 0; i < 8; i++) {
        int chunk = t + 512 * i;                 // == pseudo-group index of these 8
        const float4* p4 = (const float4*)(ri + 8 * chunk);
        float4 a = p4[0], c = p4[1];
        float v[8] = {a.x, a.y, a.z, a.w, c.x, c.y, c.z, c.w};
        bool grp = (chunk == pseudo);
#pragma unroll
        for (int j = 0; j < 8; j++) {
            m = fmaxf(m, v[j]);
            if (j == cam) mi = fmaxf(mi, v[j]);
            if (!grp) atomicAdd(&hist[fkey(v[j]) >> 21], 1u);
        }
    }
    // block max reductions
    red[t] = m; __syncthreads();
    for (int off = 256; off > 0; off >>= 1) {
        if (t < off) red[t] = fmaxf(red[t], red[t + off]);
        __syncthreads();
    }
    float M = red[0]; __syncthreads();
    red[t] = mi; __syncthreads();
    for (int off = 256; off > 0; off >>= 1) {
        if (t < off) red[t] = fmaxf(red[t], red[t + off]);
        __syncthreads();
    }
    float Mi = red[0]; __syncthreads();

    // suffix scan over 2048 bins (4 per thread) to locate top-BGK boundary
    {
        unsigned cs = hist[t*4] + hist[t*4+1] + hist[t*4+2] + hist[t*4+3];
        sa[t] = cs; __syncthreads();
        unsigned* src = sa; unsigned* dst = sb2;
        for (int off = 1; off < 512; off <<= 1) {
            unsigned x = src[t] + ((t + off < 512) ? src[t + off] : 0u);
            __syncthreads();
            dst[t] = x; __syncthreads();
            unsigned* tmp = src; src = dst; dst = tmp;
        }
        unsigned running = (t < 511) ? src[t + 1] : 0u;
        for (int g = 3; g >= 0; g--) {
            int bin = t * 4 + g;
            unsigned h = hist[bin];
            if (running < (unsigned)BGK && running + h >= (unsigned)BGK) {
                sh_bstar = bin; sh_cnt = (int)running;
            }
            running += h;
        }
    }
    __syncthreads();
    int bstar = sh_bstar, needc = BGK - sh_cnt;

    // pass 2: cross exp-sum over > boundary, boundary candidates, intra exp-sum
    float seC = 0.f, seI = 0.f;
#pragma unroll
    for (int i = 0; i < 8; i++) {
        int chunk = t + 512 * i;
        const float4* p4 = (const float4*)(ri + 8 * chunk);
        float4 a = p4[0], c = p4[1];
        float v[8] = {a.x, a.y, a.z, a.w, c.x, c.y, c.z, c.w};
        bool grp = (chunk == pseudo);
#pragma unroll
        for (int j = 0; j < 8; j++) {
            if (j == cam) seI += __expf(v[j] - Mi);
            if (!grp) {
                int bin = (int)(fkey(v[j]) >> 21);
                if (bin > bstar) seC += __expf(v[j] - M);
                else if (bin == bstar) {
                    unsigned k = atomicAdd(&sh_nc, 1u);
                    if (k < 1024u) candv[k] = v[j];
                }
            }
        }
    }
    __syncthreads();
    {
        int nc = (int)min(sh_nc, 1024u);
        for (int i = t; i < nc; i += 512) {
            float v = candv[i];
            int r = 0;
            for (int j = 0; j < nc; j++) {
                float w = candv[j];
                r += (w > v) || (w == v && j < i);
            }
            if (r < needc) seC += __expf(v - M);
        }
    }
    if (t < 8) seC += __expf(sposv[t] - M);
    red[t] = seC; __syncthreads();
    for (int off = 256; off > 0; off >>= 1) {
        if (t < off) red[t] += red[t + off];
        __syncthreads();
    }
    float sumC = red[0]; __syncthreads();
    red[t] = seI; __syncthreads();
    for (int off = 256; off > 0; off >>= 1) {
        if (t < off) red[t] += red[t + off];
        __syncthreads();
    }
    if (t == 0) {
        float psum = 0.f;
        for (int k = 0; k < 8; k++) psum += sposv[k];
        g_loss[b]      = Mi + logf(red[0]) - sposv[cam];          // intra
        g_loss[BN + b] = M  + logf(sumC)   - psum * 0.125f;       // cross
    }
    __syncthreads();

    // ============ PHASE B: sims row (online) ============
    for (int i = t; i < 2048; i += 512) hist[i] = 0;
    if (t == 0) { sh_nc = 0; sh_na = 0; }
    __syncthreads();

    float bv[8]; int bi[8];
#pragma unroll
    for (int j = 0; j < 8; j++) { bv[j] = NEG_INF; bi[j] = 0x7fffffff; }
#pragma unroll
    for (int i = 0; i < 8; i++) {
        int chunk = t + 512 * i;
        const float4* p4 = (const float4*)(rs + 8 * chunk);
        float4 a = p4[0], c = p4[1];
        float v[8] = {a.x, a.y, a.z, a.w, c.x, c.y, c.z, c.w};
#pragma unroll
        for (int j = 0; j < 8; j++) {
            if (v[j] > bv[j]) { bv[j] = v[j]; bi[j] = 8 * chunk + j; }
            atomicAdd(&hist[fkey(v[j]) >> 21], 1u);
        }
    }
    // per-camera warp reduce, then serial finish
#pragma unroll
    for (int j = 0; j < 8; j++) {
        float v = bv[j]; int idx = bi[j];
        for (int off = 16; off > 0; off >>= 1) {
            float ov = __shfl_down_sync(0xffffffffu, v, off);
            int   oi = __shfl_down_sync(0xffffffffu, idx, off);
            if (ov > v || (ov == v && oi < idx)) { v = ov; idx = oi; }
        }
        if (lane == 0) { s_cv[j][wid] = v; s_ci[j][wid] = idx; }
    }
    __syncthreads();
    if (t == 0) {
        float cv[8]; int ci[8];
        for (int c = 0; c < 8; c++) {
            float bvv = NEG_INF; int bii = 0x7fffffff;
            for (int w2 = 0; w2 < 16; w2++) {
                float v = s_cv[c][w2]; int idx = s_ci[c][w2];
                if (v > bvv || (v == bvv && idx < bii)) { bvv = v; bii = idx; }
            }
            cv[c] = bvv; ci[c] = bii;
        }
        bool used[8] = {false,false,false,false,false,false,false,false};
        for (int k = 0; k < PKK; k++) {
            int bc = -1; float bvv = NEG_INF;
            for (int c = 0; c < 8; c++)
                if (!used[c] && cv[c] > bvv) { bvv = cv[c]; bc = c; }
            used[bc] = true;
            chos[k] = ci[bc]; chosv[k] = bvv;
        }
        for (int k = 0; k < PKK; k++) hist[fkey(chosv[k]) >> 21] -= 1;
    }
    __syncthreads();

    // suffix scan for top-BGK boundary over sims
    {
        unsigned cs = hist[t*4] + hist[t*4+1] + hist[t*4+2] + hist[t*4+3];
        sa[t] = cs; __syncthreads();
        unsigned* src = sa; unsigned* dst = sb2;
        for (int off = 1; off < 512; off <<= 1) {
            unsigned x = src[t] + ((t + off < 512) ? src[t + off] : 0u);
            __syncthreads();
            dst[t] = x; __syncthreads();
            unsigned* tmp = src; src = dst; dst = tmp;
        }
        unsigned running = (t < 511) ? src[t + 1] : 0u;
        for (int g = 3; g >= 0; g--) {
            int bin = t * 4 + g;
            unsigned h = hist[bin];
            if (running < (unsigned)BGK && running + h >= (unsigned)BGK) {
                sh_bstar = bin; sh_cnt = (int)running;
            }
            running += h;
        }
    }
    __syncthreads();
    int bstar2 = sh_bstar, needc2 = BGK - sh_cnt;
    int c0 = chos[0], c1 = chos[1], c2 = chos[2];

    // pass 2 over sims: collect indices above boundary + boundary candidates
#pragma unroll
    for (int i = 0; i < 8; i++) {
        int chunk = t + 512 * i;
        const float4* p4 = (const float4*)(rs + 8 * chunk);
        float4 a = p4[0], c = p4[1];
        float v[8] = {a.x, a.y, a.z, a.w, c.x, c.y, c.z, c.w};
#pragma unroll
        for (int j = 0; j < 8; j++) {
            int p = 8 * chunk + j;
            if (p == c0 || p == c1 || p == c2) continue;
            int bin = (int)(fkey(v[j]) >> 21);
            if (bin > bstar2) {
                unsigned k = atomicAdd(&sh_na, 1u);
                if (k < 64u) above[k] = p;
            } else if (bin == bstar2) {
                unsigned k = atomicAdd(&sh_nc, 1u);
                if (k < 1024u) { candv[k] = v[j]; candi[k] = p; }
            }
        }
    }
    __syncthreads();
    int na = (int)min(sh_na, 64u);
    int nc = (int)min(sh_nc, 1024u);
    if (t == 0) { sh_nf = 3 + (unsigned)na; fin[0] = c0; fin[1] = c1; fin[2] = c2; }
    __syncthreads();
    for (int i = t; i < na; i += 512) fin[3 + i] = above[i];
    for (int i = t; i < nc; i += 512) {
        float v = candv[i]; int pi = candi[i];
        int r = 0;
        for (int j = 0; j < nc; j++) {
            float wv = candv[j];
            r += (wv > v) || (wv == v && candi[j] < pi);
        }
        if (r < needc2) {
            unsigned k = atomicAdd(&sh_nf, 1u);
            if (k < 64u) fin[k] = pi;
        }
    }
    __syncthreads();
    int nf = (int)min(sh_nf, 64u);   // 53

    float val = (t < nf) ? ri[fin[t]] : NEG_INF;
    red[t] = val; __syncthreads();
    for (int off = 256; off > 0; off >>= 1) {
        if (t < off) red[t] = fmaxf(red[t], red[t + off]);
        __syncthreads();
    }
    float mo = red[0]; __syncthreads();
    red[t] = (t < nf) ? __expf(val - mo) : 0.f;
    __syncthreads();
    for (int off = 256; off > 0; off >>= 1) {
        if (t < off) red[t] += red[t + off];
        __syncthreads();
    }
    if (t == 0) {
        float csum = ri[c0] + ri[c1] + ri[c2];
        g_loss[2 * BN + b] = mo + logf(red[0]) - csum * (1.0f / 3.0f);
    }
}

// ---------------- final reduction ----------------
__global__ void k_final(const int* __restrict__ cams, float* __restrict__ out) {
    __shared__ float s[8];
    int t = threadIdx.x;
    if (t < 8) {
        float acc = 0.f; int n = 0;
        for (int b = 0; b < BN; b++) {
            if (cams[b] == t) {
                acc += g_loss[b] + g_loss[BN + b] + g_loss[2 * BN + b];
                n++;
            }
        }
        s[t] = (n > 0) ? acc / (float)n : 0.f;
    }
    __syncthreads();
    if (t == 0) {
        float tot = 0.f;
        for (int c = 0; c < 8; c++) tot += s[c];
        out[0] = tot;
    }
}

// ---------------- launch ----------------
extern "C" void kernel_launch(void* const* d_in, const int* in_sizes, int n_in,
                              void* d_out, int out_size) {
    const float* features        = (const float*)d_in[0];
    const int*   targets         = (const int*)d_in[1];
    const int*   cams            = (const int*)d_in[2];
    const float* global_memory   = (const float*)d_in[4];
    const int*   all_proxy_label = (const int*)d_in[6];
    float* out = (float*)d_out;

    k_prep<<<BN, DN>>>(features, targets, all_proxy_label, global_memory);
    dim3 gg(PN / 128, BN / 64);
    k_gemm<<<gg, 256>>>(global_memory);
    k_loss<<<BN, 512>>>(cams);
    k_final<<<1, 32>>>(cams, out);
}